// round 1
// baseline (speedup 1.0000x reference)
#include <cuda_runtime.h>

#define NN   100000
#define NE   1600000
#define NG   4096
#define HD   128
#define FIN  11
#define FOUT 19

// Scratch (static __device__ — no allocation allowed).
// bufA: hs1 then hs2 ; bufB: acc1 then h1 (in place) ; bufC: acc2
__device__ float4 g_bufA[NN * 32];
__device__ float4 g_bufB[NN * 32];
__device__ float4 g_bufC[NN * 32];
__device__ float4 g_pool[NG * 32];
__device__ float  g_deg[NN];
__device__ float  g_dinv[NN];
__device__ float  g_cnt[NG];

// ---------------------------------------------------------------- zero scratch
__global__ void k_zeroall() {
    size_t tid = (size_t)blockIdx.x * blockDim.x + threadIdx.x;
    size_t stride = (size_t)gridDim.x * blockDim.x;
    float4 z = make_float4(0.f, 0.f, 0.f, 0.f);
    for (size_t i = tid; i < (size_t)NN * 32; i += stride) { g_bufB[i] = z; g_bufC[i] = z; }
    for (size_t i = tid; i < (size_t)NG * 32; i += stride) g_pool[i] = z;
    for (size_t i = tid; i < NN; i += stride) g_deg[i] = 0.f;
    for (size_t i = tid; i < NG; i += stride) g_cnt[i] = 0.f;
}

// ------------------------------------------- degree (edges at dst) + pool cnts
__global__ void k_degcnt(const int* __restrict__ dst, const int* __restrict__ batch) {
    int tid = blockIdx.x * blockDim.x + threadIdx.x;
    int stride = gridDim.x * blockDim.x;
    for (int e = tid; e < NE; e += stride) atomicAdd(&g_deg[dst[e]], 1.f);
    for (int i = tid; i < NN; i += stride) atomicAdd(&g_cnt[batch[i]], 1.f);
}

// dinv = rsqrt(deg_in + 1 self loop)
__global__ void k_dinv() {
    int i = blockIdx.x * blockDim.x + threadIdx.x;
    if (i < NN) g_dinv[i] = rsqrtf(g_deg[i] + 1.f);
}

// ----------------------------------------------- hs1 = (x @ W1) * dinv  (K=11)
__global__ void k_xw1(const float* __restrict__ x, const float* __restrict__ W1) {
    int idx = blockIdx.x * blockDim.x + threadIdx.x;
    if (idx >= NN * HD) return;
    int i = idx >> 7, f = idx & 127;
    const float* xr = x + i * FIN;
    float s = 0.f;
#pragma unroll
    for (int k = 0; k < FIN; k++) s += xr[k] * W1[k * HD + f];
    ((float*)g_bufA)[idx] = s * g_dinv[i];
}

// ----------------------- edge scatter: acc[dst] += hs[src]   (1 warp per edge)
__global__ void k_scatter(const int* __restrict__ src, const int* __restrict__ dst, int layer) {
    float4* acc = (layer == 0) ? g_bufB : g_bufC;
    const float4* hs = g_bufA;
    int lane = threadIdx.x & 31;
    int warp = (blockIdx.x * blockDim.x + threadIdx.x) >> 5;
    int nw = (gridDim.x * blockDim.x) >> 5;
    for (int e = warp; e < NE; e += nw) {
        int s = __ldg(src + e);
        int d = __ldg(dst + e);
        float4 v = hs[(size_t)s * 32 + lane];
        atomicAdd(&acc[(size_t)d * 32 + lane], v);   // RED.v4.f32 on sm_90+
    }
}

// -------------------- h1 = relu(dinv*(acc1 + hs1) + b1)  written over acc1 buf
__global__ void k_fin1(const float* __restrict__ b1) {
    int idx = blockIdx.x * blockDim.x + threadIdx.x;
    if (idx >= NN * HD) return;
    int i = idx >> 7, f = idx & 127;
    float* A = (float*)g_bufA;
    float* B = (float*)g_bufB;
    float v = g_dinv[i] * (B[idx] + A[idx]) + b1[f];
    B[idx] = v > 0.f ? v : 0.f;
}

// ------------------------------- hs2 = (h1 @ W2) * dinv : tiled fp32 SIMT GEMM
// block = 128 threads (one per output col), 32 node rows per block.
// W2 transposed into padded smem (stride 132 floats -> conflict-free float4).
#define GEMM_M 32
#define W2PAD 132
__global__ void k_gemm(const float* __restrict__ W2) {
    __shared__ float4 hT[GEMM_M][32];          // 32 rows x 128 floats = 16 KB
    extern __shared__ float w2t[];             // [128][W2PAD] n-major, 67.6 KB
    const float* h1 = (const float*)g_bufB;
    float* hs2 = (float*)g_bufA;

    for (int idx = threadIdx.x; idx < HD * HD; idx += blockDim.x) {
        int k = idx >> 7, n = idx & 127;
        w2t[n * W2PAD + k] = W2[idx];
    }
    int m0 = blockIdx.x * GEMM_M;
    for (int idx = threadIdx.x; idx < GEMM_M * 32; idx += blockDim.x) {
        int m = idx >> 5, k4 = idx & 31;
        hT[m][k4] = ((const float4*)h1)[(size_t)(m0 + m) * 32 + k4];
    }
    __syncthreads();

    int n = threadIdx.x;
    const float* wrow = w2t + n * W2PAD;
    float acc[GEMM_M];
#pragma unroll
    for (int m = 0; m < GEMM_M; m++) acc[m] = 0.f;

    for (int k4 = 0; k4 < 32; k4++) {
        float4 w = *(const float4*)(wrow + k4 * 4);
#pragma unroll
        for (int m = 0; m < GEMM_M; m++) {
            float4 h = hT[m][k4];
            acc[m] += h.x * w.x + h.y * w.y + h.z * w.z + h.w * w.w;
        }
    }
#pragma unroll
    for (int m = 0; m < GEMM_M; m++)
        hs2[(size_t)(m0 + m) * HD + n] = acc[m] * g_dinv[m0 + m];
}

// ---------- h2 = dinv*(acc2 + hs2) + b2 ; pool[batch[i]] += h2 (float4 RED)
__global__ void k_fin2pool(const int* __restrict__ batch, const float* __restrict__ b2) {
    int idx = blockIdx.x * blockDim.x + threadIdx.x;
    if (idx >= NN * 32) return;
    int i = idx >> 5, q = idx & 31;
    float4 a = g_bufC[idx];
    float4 h = g_bufA[idx];
    float4 b = ((const float4*)b2)[q];
    float di = g_dinv[i];
    float4 r;
    r.x = di * (a.x + h.x) + b.x;
    r.y = di * (a.y + h.y) + b.y;
    r.z = di * (a.z + h.z) + b.z;
    r.w = di * (a.w + h.w) + b.w;
    atomicAdd(&g_pool[(size_t)batch[i] * 32 + q], r);
}

// ------------------------------- out[g] = (pool[g]/max(cnt,1)) @ Wlin + blin
__global__ void k_out(const float* __restrict__ Wlin, const float* __restrict__ blin,
                      float* __restrict__ out) {
    __shared__ float p[HD];
    int g = blockIdx.x;
    int t = threadIdx.x;
    float c = g_cnt[g];
    c = (c < 1.f) ? 1.f : c;
    p[t] = ((const float*)g_pool)[(size_t)g * HD + t] / c;
    __syncthreads();
    if (t < FOUT) {
        float s = blin[t];
#pragma unroll 8
        for (int k = 0; k < HD; k++) s += p[k] * Wlin[k * FOUT + t];
        out[(size_t)g * FOUT + t] = s;
    }
}

extern "C" void kernel_launch(void* const* d_in, const int* in_sizes, int n_in,
                              void* d_out, int out_size) {
    (void)in_sizes; (void)n_in; (void)out_size;
    const float* x    = (const float*)d_in[0];
    const int*   esrc = (const int*)d_in[1];
    const int*   edst = (const int*)d_in[2];
    const int*   batch= (const int*)d_in[3];
    const float* W1   = (const float*)d_in[4];
    const float* b1   = (const float*)d_in[5];
    const float* W2   = (const float*)d_in[6];
    const float* b2   = (const float*)d_in[7];
    const float* Wlin = (const float*)d_in[8];
    const float* blin = (const float*)d_in[9];
    float* out = (float*)d_out;

    const int DSMEM = HD * W2PAD * (int)sizeof(float);   // 67584 B
    cudaFuncSetAttribute(k_gemm, cudaFuncAttributeMaxDynamicSharedMemorySize, DSMEM);

    k_zeroall<<<2048, 256>>>();
    k_degcnt<<<2048, 256>>>(edst, batch);
    k_dinv<<<(NN + 255) / 256, 256>>>();
    k_xw1<<<(NN * HD) / 256, 256>>>(x, W1);
    k_scatter<<<4096, 256>>>(esrc, edst, 0);
    k_fin1<<<(NN * HD) / 256, 256>>>(b1);
    k_gemm<<<NN / GEMM_M, 128, DSMEM>>>(W2);
    k_scatter<<<4096, 256>>>(esrc, edst, 1);
    k_fin2pool<<<(NN * 32) / 256, 256>>>(batch, b2);
    k_out<<<NG, HD>>>(Wlin, blin, out);
}

// round 2
// speedup vs baseline: 2.7073x; 2.7073x over previous
#include <cuda_runtime.h>

#define NN   100000
#define NE   1600000
#define NG   4096
#define HD   128
#define FIN  11
#define FOUT 19
#define NBLK 196          // ceil(NN/512) scan blocks

// ----------------------------------------------------------------- scratch
__device__ float4 g_hs[NN * 32];      // hs1 then hs2 = (h@W)*dinv
__device__ float4 g_h1[NN * 32];      // relu'd layer-1 output
__device__ float4 g_pool[NG * 32];
__device__ int    g_deg_i[NN];
__device__ int    g_rowptr[NN + 1];
__device__ int    g_wpos[NN];
__device__ int    g_csr[NE];
__device__ int    g_bsum[256];
__device__ int    g_boff[256];
__device__ int    g_cnt_i[NG];
__device__ float  g_dinv[NN];

__device__ __forceinline__ unsigned long long ffma2(unsigned long long a,
                                                    unsigned long long b,
                                                    unsigned long long c) {
    unsigned long long d;
    asm("fma.rn.f32x2 %0, %1, %2, %3;" : "=l"(d) : "l"(a), "l"(b), "l"(c));
    return d;
}
__device__ __forceinline__ unsigned long long packf2(float lo, float hi) {
    unsigned long long r;
    asm("mov.b64 %0, {%1, %2};" : "=l"(r) : "f"(lo), "f"(hi));
    return r;
}
__device__ __forceinline__ void unpackf2(unsigned long long v, float& lo, float& hi) {
    asm("mov.b64 {%0, %1}, %2;" : "=f"(lo), "=f"(hi) : "l"(v));
}

// -------------------------------------------------------------- zero (small)
__global__ void k_zero() {
    int tid = blockIdx.x * blockDim.x + threadIdx.x;
    int stride = gridDim.x * blockDim.x;
    float4 z = make_float4(0.f, 0.f, 0.f, 0.f);
    for (int i = tid; i < NG * 32; i += stride) g_pool[i] = z;
    for (int i = tid; i < NN; i += stride) g_deg_i[i] = 0;
    for (int i = tid; i < NG; i += stride) g_cnt_i[i] = 0;
}

// ------------------------------------------------ histogram: in-degree + cnt
__global__ void k_degcnt(const int* __restrict__ dst, const int* __restrict__ batch) {
    int tid = blockIdx.x * blockDim.x + threadIdx.x;
    int stride = gridDim.x * blockDim.x;
    for (int e = tid; e < NE; e += stride) atomicAdd(&g_deg_i[dst[e]], 1);
    for (int i = tid; i < NN; i += stride) atomicAdd(&g_cnt_i[batch[i]], 1);
}

// ------------------------------------------------------- 3-kernel excl. scan
__global__ void k_scanA() {
    __shared__ int sh[512];
    int i = blockIdx.x * 512 + threadIdx.x;
    sh[threadIdx.x] = (i < NN) ? g_deg_i[i] : 0;
    __syncthreads();
    for (int s = 256; s > 0; s >>= 1) {
        if (threadIdx.x < s) sh[threadIdx.x] += sh[threadIdx.x + s];
        __syncthreads();
    }
    if (threadIdx.x == 0) g_bsum[blockIdx.x] = sh[0];
}
__global__ void k_scanB() {
    __shared__ int sh[256];
    int t = threadIdx.x;
    int v = (t < NBLK) ? g_bsum[t] : 0;
    sh[t] = v;
    __syncthreads();
    for (int off = 1; off < 256; off <<= 1) {
        int add = (t >= off) ? sh[t - off] : 0;
        __syncthreads();
        sh[t] += add;
        __syncthreads();
    }
    g_boff[t] = sh[t] - v;
}
__global__ void k_scanC() {
    __shared__ int sh[512];
    int t = threadIdx.x;
    int i = blockIdx.x * 512 + t;
    int v = (i < NN) ? g_deg_i[i] : 0;
    sh[t] = v;
    __syncthreads();
    for (int off = 1; off < 512; off <<= 1) {
        int add = (t >= off) ? sh[t - off] : 0;
        __syncthreads();
        sh[t] += add;
        __syncthreads();
    }
    int excl = sh[t] - v + g_boff[blockIdx.x];
    if (i < NN) { g_rowptr[i] = excl; g_wpos[i] = excl; }
    if (i == NN - 1) g_rowptr[NN] = excl + v;
}

// ------------------------------------------------------------------ CSR fill
__global__ void k_fill(const int* __restrict__ src, const int* __restrict__ dst) {
    int tid = blockIdx.x * blockDim.x + threadIdx.x;
    int stride = gridDim.x * blockDim.x;
    for (int e = tid; e < NE; e += stride) {
        int d = dst[e];
        int p = atomicAdd(&g_wpos[d], 1);
        g_csr[p] = src[e];
    }
}

__global__ void k_dinv() {
    int i = blockIdx.x * blockDim.x + threadIdx.x;
    if (i < NN) g_dinv[i] = rsqrtf((float)g_deg_i[i] + 1.f);
}

// --------------------------------- hs1 = (x@W1)*dinv, warp per node (K = 11)
__global__ void k_xw1(const float* __restrict__ x, const float* __restrict__ W1) {
    int gw = (blockIdx.x * blockDim.x + threadIdx.x) >> 5;
    int lane = threadIdx.x & 31;
    if (gw >= NN) return;
    float xv = (lane < FIN) ? __ldg(x + (size_t)gw * FIN + lane) : 0.f;
    const float4* W4 = (const float4*)W1;
    float4 acc = make_float4(0.f, 0.f, 0.f, 0.f);
#pragma unroll
    for (int k = 0; k < FIN; k++) {
        float xk = __shfl_sync(0xffffffffu, xv, k);
        float4 w = __ldg(&W4[k * 32 + lane]);
        acc.x = fmaf(xk, w.x, acc.x);
        acc.y = fmaf(xk, w.y, acc.y);
        acc.z = fmaf(xk, w.z, acc.z);
        acc.w = fmaf(xk, w.w, acc.w);
    }
    float di = g_dinv[gw];
    acc.x *= di; acc.y *= di; acc.z *= di; acc.w *= di;
    g_hs[(size_t)gw * 32 + lane] = acc;
}

// -------- gather layer 1: h1 = relu(dinv*(hs1[self] + sum hs1[src]) + b1)
__device__ __forceinline__ void acc4(float4& a, float4 v) {
    a.x += v.x; a.y += v.y; a.z += v.z; a.w += v.w;
}
__global__ void k_gather1(const float* __restrict__ b1) {
    int gw = (blockIdx.x * blockDim.x + threadIdx.x) >> 5;
    if (gw >= NN) return;
    int lane = threadIdx.x & 31;
    const float4* hs = g_hs;
    int beg = __ldg(&g_rowptr[gw]);
    int end = __ldg(&g_rowptr[gw + 1]);
    float4 acc = hs[(size_t)gw * 32 + lane];
    int j = beg;
    for (; j + 3 < end; j += 4) {
        int s0 = __ldg(g_csr + j), s1 = __ldg(g_csr + j + 1);
        int s2 = __ldg(g_csr + j + 2), s3 = __ldg(g_csr + j + 3);
        float4 v0 = hs[(size_t)s0 * 32 + lane];
        float4 v1 = hs[(size_t)s1 * 32 + lane];
        float4 v2 = hs[(size_t)s2 * 32 + lane];
        float4 v3 = hs[(size_t)s3 * 32 + lane];
        acc4(acc, v0); acc4(acc, v1); acc4(acc, v2); acc4(acc, v3);
    }
    for (; j < end; j++) {
        int s = __ldg(g_csr + j);
        acc4(acc, hs[(size_t)s * 32 + lane]);
    }
    float di = g_dinv[gw];
    float4 b = __ldg(&((const float4*)b1)[lane]);
    float4 r;
    r.x = fmaxf(fmaf(di, acc.x, b.x), 0.f);
    r.y = fmaxf(fmaf(di, acc.y, b.y), 0.f);
    r.z = fmaxf(fmaf(di, acc.z, b.z), 0.f);
    r.w = fmaxf(fmaf(di, acc.w, b.w), 0.f);
    g_h1[(size_t)gw * 32 + lane] = r;
}

// ------------------- hs2 = (h1 @ W2) * dinv : f32x2 packed-FMA SIMT GEMM
// block = 256 thr, tile = 64 m-rows x 128 n-cols; thread: 1 col x 32 rows
#define GM 64
#define WPAD 129
#define HPAD 33
__global__ void k_gemm(const float* __restrict__ W2) {
    extern __shared__ float smem_[];
    float* w2t = smem_;                                              // [128][129]
    unsigned long long* hP = (unsigned long long*)(smem_ + HD * WPAD); // [128][33] m-pairs
    const float* h1 = (const float*)g_h1;
    float* hs2 = (float*)g_hs;
    int tid = threadIdx.x;

    for (int idx = tid; idx < HD * HD; idx += 256) {
        int k = idx >> 7, n = idx & 127;
        w2t[n * WPAD + k] = W2[idx];
    }
    int m0 = blockIdx.x * GM;
    for (int idx = tid; idx < 32 * HD; idx += 256) {
        int mp = idx >> 7, k = idx & 127;
        int r0 = m0 + 2 * mp;
        float a = h1[(size_t)min(r0, NN - 1) * HD + k];
        float b = h1[(size_t)min(r0 + 1, NN - 1) * HD + k];
        hP[k * HPAD + mp] = packf2(a, b);
    }
    __syncthreads();

    int n = tid & 127;
    int mh = tid >> 7;    // 0/1 -> which 32-row half
    const float* wrow = w2t + n * WPAD;
    unsigned long long acc[16];
#pragma unroll
    for (int i = 0; i < 16; i++) acc[i] = 0ull;

#pragma unroll 4
    for (int k = 0; k < HD; k++) {
        float w = wrow[k];
        unsigned long long wd = packf2(w, w);
        const unsigned long long* hk = hP + k * HPAD + mh * 16;
#pragma unroll
        for (int mp = 0; mp < 16; mp++) acc[mp] = ffma2(hk[mp], wd, acc[mp]);
    }
#pragma unroll
    for (int mp = 0; mp < 16; mp++) {
        int r0 = m0 + mh * 32 + 2 * mp;
        float lo, hi;
        unpackf2(acc[mp], lo, hi);
        if (r0 < NN)     hs2[(size_t)r0 * HD + n]       = lo * g_dinv[r0];
        if (r0 + 1 < NN) hs2[(size_t)(r0 + 1) * HD + n] = hi * g_dinv[r0 + 1];
    }
}

// ------- gather layer 2 + pool: pool[batch] += dinv*(hs2[self]+sum)+b2
__global__ void k_gather2(const int* __restrict__ batch, const float* __restrict__ b2) {
    int gw = (blockIdx.x * blockDim.x + threadIdx.x) >> 5;
    if (gw >= NN) return;
    int lane = threadIdx.x & 31;
    const float4* hs = g_hs;
    int beg = __ldg(&g_rowptr[gw]);
    int end = __ldg(&g_rowptr[gw + 1]);
    float4 acc = hs[(size_t)gw * 32 + lane];
    int j = beg;
    for (; j + 3 < end; j += 4) {
        int s0 = __ldg(g_csr + j), s1 = __ldg(g_csr + j + 1);
        int s2 = __ldg(g_csr + j + 2), s3 = __ldg(g_csr + j + 3);
        float4 v0 = hs[(size_t)s0 * 32 + lane];
        float4 v1 = hs[(size_t)s1 * 32 + lane];
        float4 v2 = hs[(size_t)s2 * 32 + lane];
        float4 v3 = hs[(size_t)s3 * 32 + lane];
        acc4(acc, v0); acc4(acc, v1); acc4(acc, v2); acc4(acc, v3);
    }
    for (; j < end; j++) {
        int s = __ldg(g_csr + j);
        acc4(acc, hs[(size_t)s * 32 + lane]);
    }
    float di = g_dinv[gw];
    float4 b = __ldg(&((const float4*)b2)[lane]);
    float4 r;
    r.x = fmaf(di, acc.x, b.x);
    r.y = fmaf(di, acc.y, b.y);
    r.z = fmaf(di, acc.z, b.z);
    r.w = fmaf(di, acc.w, b.w);
    atomicAdd(&g_pool[(size_t)__ldg(&batch[gw]) * 32 + lane], r);
}

// ------------------------------- out[g] = (pool[g]/max(cnt,1)) @ Wlin + blin
__global__ void k_out(const float* __restrict__ Wlin, const float* __restrict__ blin,
                      float* __restrict__ out) {
    __shared__ float p[HD];
    int g = blockIdx.x;
    int t = threadIdx.x;
    float c = (float)g_cnt_i[g];
    c = (c < 1.f) ? 1.f : c;
    p[t] = ((const float*)g_pool)[(size_t)g * HD + t] / c;
    __syncthreads();
    if (t < FOUT) {
        float s = blin[t];
#pragma unroll 8
        for (int k = 0; k < HD; k++) s = fmaf(p[k], Wlin[k * FOUT + t], s);
        out[(size_t)g * FOUT + t] = s;
    }
}

extern "C" void kernel_launch(void* const* d_in, const int* in_sizes, int n_in,
                              void* d_out, int out_size) {
    (void)in_sizes; (void)n_in; (void)out_size;
    const float* x     = (const float*)d_in[0];
    const int*   esrc  = (const int*)d_in[1];
    const int*   edst  = (const int*)d_in[2];
    const int*   batch = (const int*)d_in[3];
    const float* W1    = (const float*)d_in[4];
    const float* b1    = (const float*)d_in[5];
    const float* W2    = (const float*)d_in[6];
    const float* b2    = (const float*)d_in[7];
    const float* Wlin  = (const float*)d_in[8];
    const float* blin  = (const float*)d_in[9];
    float* out = (float*)d_out;

    const int DSMEM = HD * WPAD * (int)sizeof(float) + HD * HPAD * 8;  // 99840 B
    cudaFuncSetAttribute(k_gemm, cudaFuncAttributeMaxDynamicSharedMemorySize, DSMEM);

    k_zero<<<512, 256>>>();
    k_degcnt<<<2048, 256>>>(edst, batch);
    k_scanA<<<NBLK, 512>>>();
    k_scanB<<<1, 256>>>();
    k_scanC<<<NBLK, 512>>>();
    k_fill<<<2048, 256>>>(esrc, edst);
    k_dinv<<<(NN + 255) / 256, 256>>>();
    k_xw1<<<12500, 256>>>(x, W1);
    k_gather1<<<12500, 256>>>(b1);
    k_gemm<<<(NN + GM - 1) / GM, 256, DSMEM>>>(W2);
    k_gather2<<<12500, 256>>>(batch, b2);
    k_out<<<NG, HD>>>(Wlin, blin, out);
}

// round 3
// speedup vs baseline: 3.2031x; 1.1831x over previous
#include <cuda_runtime.h>
#include <cuda_fp16.h>

#define NN   100000
#define NE   1600000
#define NG   4096
#define HD   128
#define FIN  11
#define FOUT 19
#define NBLK 196          // ceil(NN/512) scan blocks

// ----------------------------------------------------------------- scratch
// feature rows stored fp16: one row = 128 half = 32 uint2 (256 B)
__device__ uint2  g_hs[NN * 32];      // hs1 then hs2 = (h@W)*dinv  (fp16)
__device__ uint2  g_h1[NN * 32];      // relu'd layer-1 output      (fp16)
__device__ float4 g_pool[NG * 32];
__device__ int    g_deg_i[NN];
__device__ int    g_rowptr[NN + 1];
__device__ int    g_wpos[NN];
__device__ int    g_csr[NE];
__device__ int    g_bsum[256];
__device__ int    g_boff[256];
__device__ int    g_cnt_i[NG];
__device__ float  g_dinv[NN];

__device__ __forceinline__ unsigned long long ffma2(unsigned long long a,
                                                    unsigned long long b,
                                                    unsigned long long c) {
    unsigned long long d;
    asm("fma.rn.f32x2 %0, %1, %2, %3;" : "=l"(d) : "l"(a), "l"(b), "l"(c));
    return d;
}
__device__ __forceinline__ unsigned long long packf2(float lo, float hi) {
    unsigned long long r;
    asm("mov.b64 %0, {%1, %2};" : "=l"(r) : "f"(lo), "f"(hi));
    return r;
}
__device__ __forceinline__ void unpackf2(unsigned long long v, float& lo, float& hi) {
    asm("mov.b64 {%0, %1}, %2;" : "=f"(lo), "=f"(hi) : "l"(v));
}

// -------------------------------------------------------------- zero (small)
__global__ void k_zero() {
    int tid = blockIdx.x * blockDim.x + threadIdx.x;
    int stride = gridDim.x * blockDim.x;
    float4 z = make_float4(0.f, 0.f, 0.f, 0.f);
    for (int i = tid; i < NG * 32; i += stride) g_pool[i] = z;
    for (int i = tid; i < NN; i += stride) g_deg_i[i] = 0;
    for (int i = tid; i < NG; i += stride) g_cnt_i[i] = 0;
}

// ------------------------------------------------ histogram: in-degree + cnt
__global__ void k_degcnt(const int* __restrict__ dst, const int* __restrict__ batch) {
    int tid = blockIdx.x * blockDim.x + threadIdx.x;
    int stride = gridDim.x * blockDim.x;
    for (int e = tid; e < NE; e += stride) atomicAdd(&g_deg_i[dst[e]], 1);
    for (int i = tid; i < NN; i += stride) atomicAdd(&g_cnt_i[batch[i]], 1);
}

// ------------------------------------------------------- 3-kernel excl. scan
__global__ void k_scanA() {
    __shared__ int sh[512];
    int i = blockIdx.x * 512 + threadIdx.x;
    sh[threadIdx.x] = (i < NN) ? g_deg_i[i] : 0;
    __syncthreads();
    for (int s = 256; s > 0; s >>= 1) {
        if (threadIdx.x < s) sh[threadIdx.x] += sh[threadIdx.x + s];
        __syncthreads();
    }
    if (threadIdx.x == 0) g_bsum[blockIdx.x] = sh[0];
}
__global__ void k_scanB() {
    int t = threadIdx.x;
    int lane = t & 31, w = t >> 5;
    int v = (t < NBLK) ? g_bsum[t] : 0;
    int s = v;
#pragma unroll
    for (int o = 1; o < 32; o <<= 1) {
        int n = __shfl_up_sync(0xffffffffu, s, o);
        if (lane >= o) s += n;
    }
    __shared__ int wsum[8];
    if (lane == 31) wsum[w] = s;
    __syncthreads();
    if (w == 0 && lane < 8) {
        int ws = wsum[lane];
#pragma unroll
        for (int o = 1; o < 8; o <<= 1) {
            int n = __shfl_up_sync(0xffu, ws, o);
            if (lane >= o) ws += n;
        }
        wsum[lane] = ws;
    }
    __syncthreads();
    int pref = (w > 0) ? wsum[w - 1] : 0;
    g_boff[t] = pref + s - v;       // exclusive
}
__global__ void k_scanC() {
    int t = threadIdx.x;
    int lane = t & 31, w = t >> 5;
    int i = blockIdx.x * 512 + t;
    int v = (i < NN) ? g_deg_i[i] : 0;
    int s = v;
#pragma unroll
    for (int o = 1; o < 32; o <<= 1) {
        int n = __shfl_up_sync(0xffffffffu, s, o);
        if (lane >= o) s += n;
    }
    __shared__ int wsum[16];
    if (lane == 31) wsum[w] = s;
    __syncthreads();
    if (w == 0 && lane < 16) {
        int ws = wsum[lane];
#pragma unroll
        for (int o = 1; o < 16; o <<= 1) {
            int n = __shfl_up_sync(0xffffu, ws, o);
            if (lane >= o) ws += n;
        }
        wsum[lane] = ws;
    }
    __syncthreads();
    int excl = s - v + ((w > 0) ? wsum[w - 1] : 0) + g_boff[blockIdx.x];
    if (i < NN) {
        g_rowptr[i] = excl;
        g_wpos[i] = excl;
        g_dinv[i] = rsqrtf((float)v + 1.f);   // fused dinv
    }
    if (i == NN - 1) g_rowptr[NN] = excl + v;
}

// ------------------------------------------------------------------ CSR fill
__global__ void k_fill(const int* __restrict__ src, const int* __restrict__ dst) {
    int tid = blockIdx.x * blockDim.x + threadIdx.x;
    int stride = gridDim.x * blockDim.x;
    for (int e = tid; e < NE; e += stride) {
        int d = dst[e];
        int p = atomicAdd(&g_wpos[d], 1);
        g_csr[p] = src[e];
    }
}

// --------------------------------- hs1 = (x@W1)*dinv, warp per node (K = 11)
__global__ void k_xw1(const float* __restrict__ x, const float* __restrict__ W1) {
    int gw = (blockIdx.x * blockDim.x + threadIdx.x) >> 5;
    int lane = threadIdx.x & 31;
    if (gw >= NN) return;
    float xv = (lane < FIN) ? __ldg(x + (size_t)gw * FIN + lane) : 0.f;
    const float4* W4 = (const float4*)W1;
    float4 acc = make_float4(0.f, 0.f, 0.f, 0.f);
#pragma unroll
    for (int k = 0; k < FIN; k++) {
        float xk = __shfl_sync(0xffffffffu, xv, k);
        float4 w = __ldg(&W4[k * 32 + lane]);
        acc.x = fmaf(xk, w.x, acc.x);
        acc.y = fmaf(xk, w.y, acc.y);
        acc.z = fmaf(xk, w.z, acc.z);
        acc.w = fmaf(xk, w.w, acc.w);
    }
    float di = g_dinv[gw];
    __half2 h01 = __floats2half2_rn(acc.x * di, acc.y * di);
    __half2 h23 = __floats2half2_rn(acc.z * di, acc.w * di);
    uint2 o;
    o.x = *(unsigned*)&h01;
    o.y = *(unsigned*)&h23;
    g_hs[(size_t)gw * 32 + lane] = o;
}

// --------- fp16 row load -> fp32 accumulate helper
__device__ __forceinline__ void acch(float4& a, uint2 v) {
    __half2 p = *(__half2*)&v.x;
    __half2 q = *(__half2*)&v.y;
    float2 fp = __half22float2(p);
    float2 fq = __half22float2(q);
    a.x += fp.x; a.y += fp.y; a.z += fq.x; a.w += fq.y;
}

// -------- gather layer 1: h1 = relu(dinv*(hs1[self] + sum hs1[src]) + b1)
__global__ void k_gather1(const float* __restrict__ b1) {
    int gw = (blockIdx.x * blockDim.x + threadIdx.x) >> 5;
    if (gw >= NN) return;
    int lane = threadIdx.x & 31;
    const uint2* hs = g_hs;
    int beg = __ldg(&g_rowptr[gw]);
    int end = __ldg(&g_rowptr[gw + 1]);
    float4 acc = make_float4(0.f, 0.f, 0.f, 0.f);
    acch(acc, hs[(size_t)gw * 32 + lane]);
    int j = beg;
    for (; j + 3 < end; j += 4) {
        int s0 = __ldg(g_csr + j), s1 = __ldg(g_csr + j + 1);
        int s2 = __ldg(g_csr + j + 2), s3 = __ldg(g_csr + j + 3);
        uint2 v0 = hs[(size_t)s0 * 32 + lane];
        uint2 v1 = hs[(size_t)s1 * 32 + lane];
        uint2 v2 = hs[(size_t)s2 * 32 + lane];
        uint2 v3 = hs[(size_t)s3 * 32 + lane];
        acch(acc, v0); acch(acc, v1); acch(acc, v2); acch(acc, v3);
    }
    for (; j < end; j++) {
        int s = __ldg(g_csr + j);
        acch(acc, hs[(size_t)s * 32 + lane]);
    }
    float di = g_dinv[gw];
    float4 b = __ldg(&((const float4*)b1)[lane]);
    float rx = fmaxf(fmaf(di, acc.x, b.x), 0.f);
    float ry = fmaxf(fmaf(di, acc.y, b.y), 0.f);
    float rz = fmaxf(fmaf(di, acc.z, b.z), 0.f);
    float rw = fmaxf(fmaf(di, acc.w, b.w), 0.f);
    __half2 h01 = __floats2half2_rn(rx, ry);
    __half2 h23 = __floats2half2_rn(rz, rw);
    uint2 o;
    o.x = *(unsigned*)&h01;
    o.y = *(unsigned*)&h23;
    g_h1[(size_t)gw * 32 + lane] = o;
}

// ------------------- hs2 = (h1 @ W2) * dinv : f32x2 packed-FMA SIMT GEMM
// block = 256 thr, tile = 64 m-rows x 128 n-cols; thread: 1 col x 32 rows
#define GM 64
#define WPAD 129
#define HPAD 33
__global__ void k_gemm(const float* __restrict__ W2) {
    extern __shared__ float smem_[];
    float* w2t = smem_;                                                // [128][129]
    unsigned long long* hP = (unsigned long long*)(smem_ + HD * WPAD); // [128][33] m-pairs
    const __half* h1 = (const __half*)g_h1;
    __half* hs2 = (__half*)g_hs;
    int tid = threadIdx.x;

    for (int idx = tid; idx < HD * HD; idx += 256) {
        int k = idx >> 7, n = idx & 127;
        w2t[n * WPAD + k] = W2[idx];
    }
    int m0 = blockIdx.x * GM;
    for (int idx = tid; idx < 32 * HD; idx += 256) {
        int mp = idx >> 7, k = idx & 127;
        int r0 = m0 + 2 * mp;
        float a = __half2float(h1[(size_t)min(r0, NN - 1) * HD + k]);
        float b = __half2float(h1[(size_t)min(r0 + 1, NN - 1) * HD + k]);
        hP[k * HPAD + mp] = packf2(a, b);
    }
    __syncthreads();

    int n = tid & 127;
    int mh = tid >> 7;    // 0/1 -> which 32-row half
    const float* wrow = w2t + n * WPAD;
    unsigned long long acc[16];
#pragma unroll
    for (int i = 0; i < 16; i++) acc[i] = 0ull;

#pragma unroll 4
    for (int k = 0; k < HD; k++) {
        float w = wrow[k];
        unsigned long long wd = packf2(w, w);
        const unsigned long long* hk = hP + k * HPAD + mh * 16;
#pragma unroll
        for (int mp = 0; mp < 16; mp++) acc[mp] = ffma2(hk[mp], wd, acc[mp]);
    }
#pragma unroll
    for (int mp = 0; mp < 16; mp++) {
        int r0 = m0 + mh * 32 + 2 * mp;
        float lo, hi;
        unpackf2(acc[mp], lo, hi);
        if (r0 < NN)     hs2[(size_t)r0 * HD + n]       = __float2half_rn(lo * g_dinv[r0]);
        if (r0 + 1 < NN) hs2[(size_t)(r0 + 1) * HD + n] = __float2half_rn(hi * g_dinv[r0 + 1]);
    }
}

// ------- gather layer 2 + pool: pool[batch] += dinv*(hs2[self]+sum)+b2
__global__ void k_gather2(const int* __restrict__ batch, const float* __restrict__ b2) {
    int gw = (blockIdx.x * blockDim.x + threadIdx.x) >> 5;
    if (gw >= NN) return;
    int lane = threadIdx.x & 31;
    const uint2* hs = g_hs;
    int beg = __ldg(&g_rowptr[gw]);
    int end = __ldg(&g_rowptr[gw + 1]);
    float4 acc = make_float4(0.f, 0.f, 0.f, 0.f);
    acch(acc, hs[(size_t)gw * 32 + lane]);
    int j = beg;
    for (; j + 3 < end; j += 4) {
        int s0 = __ldg(g_csr + j), s1 = __ldg(g_csr + j + 1);
        int s2 = __ldg(g_csr + j + 2), s3 = __ldg(g_csr + j + 3);
        uint2 v0 = hs[(size_t)s0 * 32 + lane];
        uint2 v1 = hs[(size_t)s1 * 32 + lane];
        uint2 v2 = hs[(size_t)s2 * 32 + lane];
        uint2 v3 = hs[(size_t)s3 * 32 + lane];
        acch(acc, v0); acch(acc, v1); acch(acc, v2); acch(acc, v3);
    }
    for (; j < end; j++) {
        int s = __ldg(g_csr + j);
        acch(acc, hs[(size_t)s * 32 + lane]);
    }
    float di = g_dinv[gw];
    float4 b = __ldg(&((const float4*)b2)[lane]);
    float4 r;
    r.x = fmaf(di, acc.x, b.x);
    r.y = fmaf(di, acc.y, b.y);
    r.z = fmaf(di, acc.z, b.z);
    r.w = fmaf(di, acc.w, b.w);
    atomicAdd(&g_pool[(size_t)__ldg(&batch[gw]) * 32 + lane], r);
}

// ------------------------------- out[g] = (pool[g]/max(cnt,1)) @ Wlin + blin
__global__ void k_out(const float* __restrict__ Wlin, const float* __restrict__ blin,
                      float* __restrict__ out) {
    __shared__ float p[HD];
    int g = blockIdx.x;
    int t = threadIdx.x;
    float c = (float)g_cnt_i[g];
    c = (c < 1.f) ? 1.f : c;
    p[t] = ((const float*)g_pool)[(size_t)g * HD + t] / c;
    __syncthreads();
    if (t < FOUT) {
        float s = blin[t];
#pragma unroll 8
        for (int k = 0; k < HD; k++) s = fmaf(p[k], Wlin[k * FOUT + t], s);
        out[(size_t)g * FOUT + t] = s;
    }
}

extern "C" void kernel_launch(void* const* d_in, const int* in_sizes, int n_in,
                              void* d_out, int out_size) {
    (void)in_sizes; (void)n_in; (void)out_size;
    const float* x     = (const float*)d_in[0];
    const int*   esrc  = (const int*)d_in[1];
    const int*   edst  = (const int*)d_in[2];
    const int*   batch = (const int*)d_in[3];
    const float* W1    = (const float*)d_in[4];
    const float* b1    = (const float*)d_in[5];
    const float* W2    = (const float*)d_in[6];
    const float* b2    = (const float*)d_in[7];
    const float* Wlin  = (const float*)d_in[8];
    const float* blin  = (const float*)d_in[9];
    float* out = (float*)d_out;

    const int DSMEM = HD * WPAD * (int)sizeof(float) + HD * HPAD * 8;  // 99840 B
    cudaFuncSetAttribute(k_gemm, cudaFuncAttributeMaxDynamicSharedMemorySize, DSMEM);

    k_zero<<<512, 256>>>();
    k_degcnt<<<2048, 256>>>(edst, batch);
    k_scanA<<<NBLK, 512>>>();
    k_scanB<<<1, 256>>>();
    k_scanC<<<NBLK, 512>>>();
    k_fill<<<2048, 256>>>(esrc, edst);
    k_xw1<<<12500, 256>>>(x, W1);
    k_gather1<<<12500, 256>>>(b1);
    k_gemm<<<(NN + GM - 1) / GM, 256, DSMEM>>>(W2);
    k_gather2<<<12500, 256>>>(batch, b2);
    k_out<<<NG, HD>>>(Wlin, blin, out);
}

// round 4
// speedup vs baseline: 5.0679x; 1.5822x over previous
#include <cuda_runtime.h>
#include <cuda_fp16.h>

#define NN   100000
#define NE   1600000
#define NG   4096
#define HD   128
#define FIN  11
#define FOUT 19
#define NBLK 196          // ceil(NN/512) scan blocks

// ----------------------------------------------------------------- scratch
__device__ uint2  g_hs[NN * 32];      // hs1 then hs2 (fp16 rows, 256 B each)
__device__ uint2  g_h1[NN * 32];      // relu'd layer-1 output (fp16)
__device__ float4 g_pool[NG * 32];
__device__ int    g_deg_i[NN];
__device__ int    g_rowptr[NN + 1];
__device__ int    g_wpos[NN];
__device__ int    g_csr[NE];
__device__ int    g_bsum[256];
__device__ int    g_boff[256];
__device__ int    g_cnt_i[NG];
__device__ float  g_dinv[NN];

// -------------------------------------------------------------- zero (small)
__global__ void k_zero() {
    int tid = blockIdx.x * blockDim.x + threadIdx.x;
    int stride = gridDim.x * blockDim.x;
    float4 z = make_float4(0.f, 0.f, 0.f, 0.f);
    for (int i = tid; i < NG * 32; i += stride) g_pool[i] = z;
    for (int i = tid; i < NN; i += stride) g_deg_i[i] = 0;
    for (int i = tid; i < NG; i += stride) g_cnt_i[i] = 0;
}

// ------------------------------------------------ histogram: in-degree + cnt
__global__ void k_degcnt(const int* __restrict__ dst, const int* __restrict__ batch) {
    int tid = blockIdx.x * blockDim.x + threadIdx.x;
    int stride = gridDim.x * blockDim.x;
    for (int e = tid; e < NE; e += stride) atomicAdd(&g_deg_i[dst[e]], 1);
    for (int i = tid; i < NN; i += stride) atomicAdd(&g_cnt_i[batch[i]], 1);
}

// ------------------------------------------------------- 3-kernel excl. scan
__global__ void k_scanA() {
    __shared__ int sh[512];
    int i = blockIdx.x * 512 + threadIdx.x;
    sh[threadIdx.x] = (i < NN) ? g_deg_i[i] : 0;
    __syncthreads();
    for (int s = 256; s > 0; s >>= 1) {
        if (threadIdx.x < s) sh[threadIdx.x] += sh[threadIdx.x + s];
        __syncthreads();
    }
    if (threadIdx.x == 0) g_bsum[blockIdx.x] = sh[0];
}
__global__ void k_scanB() {
    int t = threadIdx.x;
    int lane = t & 31, w = t >> 5;
    int v = (t < NBLK) ? g_bsum[t] : 0;
    int s = v;
#pragma unroll
    for (int o = 1; o < 32; o <<= 1) {
        int n = __shfl_up_sync(0xffffffffu, s, o);
        if (lane >= o) s += n;
    }
    __shared__ int wsum[8];
    if (lane == 31) wsum[w] = s;
    __syncthreads();
    if (w == 0 && lane < 8) {
        int ws = wsum[lane];
#pragma unroll
        for (int o = 1; o < 8; o <<= 1) {
            int n = __shfl_up_sync(0xffu, ws, o);
            if (lane >= o) ws += n;
        }
        wsum[lane] = ws;
    }
    __syncthreads();
    int pref = (w > 0) ? wsum[w - 1] : 0;
    g_boff[t] = pref + s - v;
}
__global__ void k_scanC() {
    int t = threadIdx.x;
    int lane = t & 31, w = t >> 5;
    int i = blockIdx.x * 512 + t;
    int v = (i < NN) ? g_deg_i[i] : 0;
    int s = v;
#pragma unroll
    for (int o = 1; o < 32; o <<= 1) {
        int n = __shfl_up_sync(0xffffffffu, s, o);
        if (lane >= o) s += n;
    }
    __shared__ int wsum[16];
    if (lane == 31) wsum[w] = s;
    __syncthreads();
    if (w == 0 && lane < 16) {
        int ws = wsum[lane];
#pragma unroll
        for (int o = 1; o < 16; o <<= 1) {
            int n = __shfl_up_sync(0xffffu, ws, o);
            if (lane >= o) ws += n;
        }
        wsum[lane] = ws;
    }
    __syncthreads();
    int excl = s - v + ((w > 0) ? wsum[w - 1] : 0) + g_boff[blockIdx.x];
    if (i < NN) {
        g_rowptr[i] = excl;
        g_wpos[i] = excl;
        g_dinv[i] = rsqrtf((float)v + 1.f);
    }
    if (i == NN - 1) g_rowptr[NN] = excl + v;
}

// ------------------------------------------------------------------ CSR fill
__global__ void k_fill(const int* __restrict__ src, const int* __restrict__ dst) {
    int tid = blockIdx.x * blockDim.x + threadIdx.x;
    int stride = gridDim.x * blockDim.x;
    for (int e = tid; e < NE; e += stride) {
        int d = dst[e];
        int p = atomicAdd(&g_wpos[d], 1);
        g_csr[p] = src[e];
    }
}

// --------------------------------- hs1 = (x@W1)*dinv, warp per node (K = 11)
__global__ void k_xw1(const float* __restrict__ x, const float* __restrict__ W1) {
    int gw = (blockIdx.x * blockDim.x + threadIdx.x) >> 5;
    int lane = threadIdx.x & 31;
    if (gw >= NN) return;
    float xv = (lane < FIN) ? __ldg(x + (size_t)gw * FIN + lane) : 0.f;
    const float4* W4 = (const float4*)W1;
    float4 acc = make_float4(0.f, 0.f, 0.f, 0.f);
#pragma unroll
    for (int k = 0; k < FIN; k++) {
        float xk = __shfl_sync(0xffffffffu, xv, k);
        float4 w = __ldg(&W4[k * 32 + lane]);
        acc.x = fmaf(xk, w.x, acc.x);
        acc.y = fmaf(xk, w.y, acc.y);
        acc.z = fmaf(xk, w.z, acc.z);
        acc.w = fmaf(xk, w.w, acc.w);
    }
    float di = g_dinv[gw];
    __half2 h01 = __floats2half2_rn(acc.x * di, acc.y * di);
    __half2 h23 = __floats2half2_rn(acc.z * di, acc.w * di);
    uint2 o;
    o.x = *(unsigned*)&h01;
    o.y = *(unsigned*)&h23;
    g_hs[(size_t)gw * 32 + lane] = o;
}

// --------- fp16 row load -> fp32 accumulate helper
__device__ __forceinline__ void acch(float4& a, uint2 v) {
    __half2 p = *(__half2*)&v.x;
    __half2 q = *(__half2*)&v.y;
    float2 fp = __half22float2(p);
    float2 fq = __half22float2(q);
    a.x += fp.x; a.y += fp.y; a.z += fq.x; a.w += fq.y;
}

// ---- gather body: acc += sum_{src in row} hs[src]; indices prefetched+shfl'd
__device__ __forceinline__ void gather_row(float4& acc, const uint2* hs,
                                           int beg, int end, int lane) {
    for (int base = beg; base < end; base += 32) {
        int j = base + lane;
        int myidx = (j < end) ? __ldg(g_csr + j) : 0;
        int cnt = min(32, end - base);
        int jj = 0;
        for (; jj + 4 <= cnt; jj += 4) {
            int s0 = __shfl_sync(0xffffffffu, myidx, jj);
            int s1 = __shfl_sync(0xffffffffu, myidx, jj + 1);
            int s2 = __shfl_sync(0xffffffffu, myidx, jj + 2);
            int s3 = __shfl_sync(0xffffffffu, myidx, jj + 3);
            uint2 v0 = hs[(size_t)s0 * 32 + lane];
            uint2 v1 = hs[(size_t)s1 * 32 + lane];
            uint2 v2 = hs[(size_t)s2 * 32 + lane];
            uint2 v3 = hs[(size_t)s3 * 32 + lane];
            acch(acc, v0); acch(acc, v1); acch(acc, v2); acch(acc, v3);
        }
        for (; jj < cnt; jj++) {
            int s = __shfl_sync(0xffffffffu, myidx, jj);
            acch(acc, hs[(size_t)s * 32 + lane]);
        }
    }
}

// -------- gather layer 1: h1 = relu(dinv*(hs1[self] + sum hs1[src]) + b1)
__global__ void k_gather1(const float* __restrict__ b1) {
    int gw = (blockIdx.x * blockDim.x + threadIdx.x) >> 5;
    if (gw >= NN) return;
    int lane = threadIdx.x & 31;
    const uint2* hs = g_hs;
    int beg = __ldg(&g_rowptr[gw]);
    int end = __ldg(&g_rowptr[gw + 1]);
    float4 acc = make_float4(0.f, 0.f, 0.f, 0.f);
    acch(acc, hs[(size_t)gw * 32 + lane]);
    gather_row(acc, hs, beg, end, lane);
    float di = g_dinv[gw];
    float4 b = __ldg(&((const float4*)b1)[lane]);
    float rx = fmaxf(fmaf(di, acc.x, b.x), 0.f);
    float ry = fmaxf(fmaf(di, acc.y, b.y), 0.f);
    float rz = fmaxf(fmaf(di, acc.z, b.z), 0.f);
    float rw = fmaxf(fmaf(di, acc.w, b.w), 0.f);
    __half2 h01 = __floats2half2_rn(rx, ry);
    __half2 h23 = __floats2half2_rn(rz, rw);
    uint2 o;
    o.x = *(unsigned*)&h01;
    o.y = *(unsigned*)&h23;
    g_h1[(size_t)gw * 32 + lane] = o;
}

// ------------------- hs2 = (h1 @ W2) * dinv : HMMA fp16 GEMM, fp32 accum
// block = 256 thr (8 warps); tile M=128, N=128, K=128. smem pad stride 136.
#define KP 136
__global__ void k_gemm(const float* __restrict__ W2) {
    extern __shared__ __half smem_[];
    __half* h1s = smem_;               // [128][KP]
    __half* w2s = smem_ + 128 * KP;    // [n=128][KP] (transposed W2, fp16)
    const __half* h1 = (const __half*)g_h1;
    __half* hs2 = (__half*)g_hs;
    int tid = threadIdx.x;
    int lane = tid & 31, w = tid >> 5;
    int m0 = blockIdx.x * 128;

    // W2 [k][n] fp32 -> w2s [n][k] fp16
    for (int idx = tid; idx < HD * HD; idx += 256) {
        int k = idx >> 7, n = idx & 127;
        w2s[n * KP + k] = __float2half_rn(W2[idx]);
    }
    // h1 tile: 8 halves (uint4) per thread x 8 iters
    for (int it = 0; it < 8; it++) {
        int idx = it * 256 + tid;            // 2048 uint4 chunks
        int m = idx >> 4, kq = idx & 15;     // kq: which 8-half chunk
        int gm = min(m0 + m, NN - 1);
        uint4 v = *(const uint4*)(h1 + (size_t)gm * HD + kq * 8);
        *(uint4*)(h1s + m * KP + kq * 8) = v;
    }
    __syncthreads();

    // warp w: rows [w*16, w*16+16)
    float acc[16][4];
#pragma unroll
    for (int nt = 0; nt < 16; nt++)
#pragma unroll
        for (int i = 0; i < 4; i++) acc[nt][i] = 0.f;

    int qr = lane >> 2;          // 0..7
    int qc = (lane & 3) * 2;     // 0,2,4,6

#pragma unroll
    for (int kt = 0; kt < 8; kt++) {
        const __half* ab = h1s + (w * 16 + qr) * KP + kt * 16 + qc;
        unsigned a0 = *(const unsigned*)(ab);
        unsigned a1 = *(const unsigned*)(ab + 8 * KP);
        unsigned a2 = *(const unsigned*)(ab + 8);
        unsigned a3 = *(const unsigned*)(ab + 8 * KP + 8);
#pragma unroll
        for (int nt = 0; nt < 16; nt++) {
            const __half* bb = w2s + (nt * 8 + qr) * KP + kt * 16 + qc;
            unsigned b0 = *(const unsigned*)(bb);
            unsigned b1 = *(const unsigned*)(bb + 8);
            asm volatile(
                "mma.sync.aligned.m16n8k16.row.col.f32.f16.f16.f32 "
                "{%0,%1,%2,%3}, {%4,%5,%6,%7}, {%8,%9}, {%0,%1,%2,%3};"
                : "+f"(acc[nt][0]), "+f"(acc[nt][1]),
                  "+f"(acc[nt][2]), "+f"(acc[nt][3])
                : "r"(a0), "r"(a1), "r"(a2), "r"(a3), "r"(b0), "r"(b1));
        }
    }

    // epilogue: scale by dinv[row], write fp16
    int r0 = m0 + w * 16 + qr;
    int r1 = r0 + 8;
    float di0 = (r0 < NN) ? g_dinv[r0] : 0.f;
    float di1 = (r1 < NN) ? g_dinv[r1] : 0.f;
#pragma unroll
    for (int nt = 0; nt < 16; nt++) {
        int c = nt * 8 + qc;
        if (r0 < NN) {
            __half2 h = __floats2half2_rn(acc[nt][0] * di0, acc[nt][1] * di0);
            *(__half2*)(hs2 + (size_t)r0 * HD + c) = h;
        }
        if (r1 < NN) {
            __half2 h = __floats2half2_rn(acc[nt][2] * di1, acc[nt][3] * di1);
            *(__half2*)(hs2 + (size_t)r1 * HD + c) = h;
        }
    }
}

// ------- gather layer 2 + pool: pool[batch] += dinv*(hs2[self]+sum)+b2
__global__ void k_gather2(const int* __restrict__ batch, const float* __restrict__ b2) {
    int gw = (blockIdx.x * blockDim.x + threadIdx.x) >> 5;
    if (gw >= NN) return;
    int lane = threadIdx.x & 31;
    const uint2* hs = g_hs;
    int beg = __ldg(&g_rowptr[gw]);
    int end = __ldg(&g_rowptr[gw + 1]);
    float4 acc = make_float4(0.f, 0.f, 0.f, 0.f);
    acch(acc, hs[(size_t)gw * 32 + lane]);
    gather_row(acc, hs, beg, end, lane);
    float di = g_dinv[gw];
    float4 b = __ldg(&((const float4*)b2)[lane]);
    float4 r;
    r.x = fmaf(di, acc.x, b.x);
    r.y = fmaf(di, acc.y, b.y);
    r.z = fmaf(di, acc.z, b.z);
    r.w = fmaf(di, acc.w, b.w);
    atomicAdd(&g_pool[(size_t)__ldg(&batch[gw]) * 32 + lane], r);
}

// ------------------------------- out[g] = (pool[g]/max(cnt,1)) @ Wlin + blin
__global__ void k_out(const float* __restrict__ Wlin, const float* __restrict__ blin,
                      float* __restrict__ out) {
    __shared__ float p[HD];
    int g = blockIdx.x;
    int t = threadIdx.x;
    float c = (float)g_cnt_i[g];
    c = (c < 1.f) ? 1.f : c;
    p[t] = ((const float*)g_pool)[(size_t)g * HD + t] / c;
    __syncthreads();
    if (t < FOUT) {
        float s = blin[t];
#pragma unroll 8
        for (int k = 0; k < HD; k++) s = fmaf(p[k], Wlin[k * FOUT + t], s);
        out[(size_t)g * FOUT + t] = s;
    }
}

extern "C" void kernel_launch(void* const* d_in, const int* in_sizes, int n_in,
                              void* d_out, int out_size) {
    (void)in_sizes; (void)n_in; (void)out_size;
    const float* x     = (const float*)d_in[0];
    const int*   esrc  = (const int*)d_in[1];
    const int*   edst  = (const int*)d_in[2];
    const int*   batch = (const int*)d_in[3];
    const float* W1    = (const float*)d_in[4];
    const float* b1    = (const float*)d_in[5];
    const float* W2    = (const float*)d_in[6];
    const float* b2    = (const float*)d_in[7];
    const float* Wlin  = (const float*)d_in[8];
    const float* blin  = (const float*)d_in[9];
    float* out = (float*)d_out;

    const int DSMEM = 2 * 128 * KP * (int)sizeof(__half);   // 69632 B
    cudaFuncSetAttribute(k_gemm, cudaFuncAttributeMaxDynamicSharedMemorySize, DSMEM);

    k_zero<<<512, 256>>>();
    k_degcnt<<<2048, 256>>>(edst, batch);
    k_scanA<<<NBLK, 512>>>();
    k_scanB<<<1, 256>>>();
    k_scanC<<<NBLK, 512>>>();
    k_fill<<<2048, 256>>>(esrc, edst);
    k_xw1<<<12500, 256>>>(x, W1);
    k_gather1<<<12500, 256>>>(b1);
    k_gemm<<<(NN + 127) / 128, 256, DSMEM>>>(W2);
    k_gather2<<<12500, 256>>>(batch, b2);
    k_out<<<NG, HD>>>(Wlin, blin, out);
}

// round 5
// speedup vs baseline: 5.1333x; 1.0129x over previous
#include <cuda_runtime.h>
#include <cuda_fp16.h>

#define NN   100000
#define NE   1600000
#define NG   4096
#define HD   128
#define FIN  11
#define FOUT 19
#define NBLK 196          // ceil(NN/512) scan blocks

// ----------------------------------------------------------------- scratch
__device__ uint2  g_hs[NN * 32];      // hs1 then hs2 (fp16 rows, 256 B each)
__device__ uint2  g_h1[NN * 32];      // relu'd layer-1 output (fp16)
__device__ float4 g_pool[NG * 32];
__device__ __half g_w2h[HD * HD];     // W2 transposed [n][k], fp16
__device__ int    g_deg_i[NN];
__device__ int    g_rowptr[NN + 1];
__device__ int    g_wpos[NN];
__device__ int    g_csr[NE];
__device__ int    g_bsum[256];
__device__ int    g_cnt_i[NG];
__device__ float  g_dinv[NN];

// ------------------------- zero counters + pool, and convert W2 -> fp16 [n][k]
__global__ void k_zero(const float* __restrict__ W2) {
    int tid = blockIdx.x * blockDim.x + threadIdx.x;
    int stride = gridDim.x * blockDim.x;
    float4 z = make_float4(0.f, 0.f, 0.f, 0.f);
    for (int i = tid; i < NG * 32; i += stride) g_pool[i] = z;
    for (int i = tid; i < NN; i += stride) g_deg_i[i] = 0;
    for (int i = tid; i < NG; i += stride) g_cnt_i[i] = 0;
    for (int i = tid; i < HD * HD; i += stride) {
        int k = i >> 7, n = i & 127;               // read coalesced over n
        g_w2h[n * HD + k] = __float2half_rn(W2[k * HD + n]);
    }
}

// ------------------------------------------------ histogram: in-degree + cnt
__global__ void k_degcnt(const int* __restrict__ dst, const int* __restrict__ batch) {
    int tid = blockIdx.x * blockDim.x + threadIdx.x;
    int stride = gridDim.x * blockDim.x;
    for (int e = tid; e < NE; e += stride) atomicAdd(&g_deg_i[dst[e]], 1);
    for (int i = tid; i < NN; i += stride) atomicAdd(&g_cnt_i[batch[i]], 1);
}

// --------------------------------------------------------- 2-kernel excl scan
__global__ void k_scanA() {
    __shared__ int sh[512];
    int i = blockIdx.x * 512 + threadIdx.x;
    sh[threadIdx.x] = (i < NN) ? g_deg_i[i] : 0;
    __syncthreads();
    for (int s = 256; s > 0; s >>= 1) {
        if (threadIdx.x < s) sh[threadIdx.x] += sh[threadIdx.x + s];
        __syncthreads();
    }
    if (threadIdx.x == 0) g_bsum[blockIdx.x] = sh[0];
}
// scanC: intra-block scan + inline prefix of g_bsum[0..bid) (replaces scanB)
__global__ void k_scanC() {
    int t = threadIdx.x;
    int lane = t & 31, w = t >> 5;
    int i = blockIdx.x * 512 + t;
    int v = (i < NN) ? g_deg_i[i] : 0;
    int s = v;
#pragma unroll
    for (int o = 1; o < 32; o <<= 1) {
        int n = __shfl_up_sync(0xffffffffu, s, o);
        if (lane >= o) s += n;
    }
    __shared__ int wsum[16];
    __shared__ int s_boff;
    if (lane == 31) wsum[w] = s;
    __syncthreads();
    if (w == 0) {
        // prefix over prior blocks' sums
        int bs = 0;
        for (int j = lane; j < blockIdx.x; j += 32) bs += g_bsum[j];
#pragma unroll
        for (int o = 16; o > 0; o >>= 1) bs += __shfl_down_sync(0xffffffffu, bs, o);
        if (lane == 0) s_boff = bs;
        // scan the 16 warp sums
        if (lane < 16) {
            int ws = wsum[lane];
#pragma unroll
            for (int o = 1; o < 16; o <<= 1) {
                int n = __shfl_up_sync(0xffffu, ws, o);
                if (lane >= o) ws += n;
            }
            wsum[lane] = ws;
        }
    }
    __syncthreads();
    int excl = s - v + ((w > 0) ? wsum[w - 1] : 0) + s_boff;
    if (i < NN) {
        g_rowptr[i] = excl;
        g_wpos[i] = excl;
        g_dinv[i] = rsqrtf((float)v + 1.f);
    }
    if (i == NN - 1) g_rowptr[NN] = excl + v;
}

// ------------------------------------------------------------------ CSR fill
__global__ void k_fill(const int* __restrict__ src, const int* __restrict__ dst) {
    int tid = blockIdx.x * blockDim.x + threadIdx.x;
    int stride = gridDim.x * blockDim.x;
    for (int e = tid; e < NE; e += stride) {
        int d = dst[e];
        int p = atomicAdd(&g_wpos[d], 1);
        g_csr[p] = src[e];
    }
}

// --------------------------------- hs1 = (x@W1)*dinv, warp per node (K = 11)
__global__ void k_xw1(const float* __restrict__ x, const float* __restrict__ W1) {
    int gw = (blockIdx.x * blockDim.x + threadIdx.x) >> 5;
    int lane = threadIdx.x & 31;
    if (gw >= NN) return;
    float xv = (lane < FIN) ? __ldg(x + (size_t)gw * FIN + lane) : 0.f;
    const float4* W4 = (const float4*)W1;
    float4 acc = make_float4(0.f, 0.f, 0.f, 0.f);
#pragma unroll
    for (int k = 0; k < FIN; k++) {
        float xk = __shfl_sync(0xffffffffu, xv, k);
        float4 w = __ldg(&W4[k * 32 + lane]);
        acc.x = fmaf(xk, w.x, acc.x);
        acc.y = fmaf(xk, w.y, acc.y);
        acc.z = fmaf(xk, w.z, acc.z);
        acc.w = fmaf(xk, w.w, acc.w);
    }
    float di = g_dinv[gw];
    __half2 h01 = __floats2half2_rn(acc.x * di, acc.y * di);
    __half2 h23 = __floats2half2_rn(acc.z * di, acc.w * di);
    uint2 o;
    o.x = *(unsigned*)&h01;
    o.y = *(unsigned*)&h23;
    g_hs[(size_t)gw * 32 + lane] = o;
}

// --------- fp16 row load -> fp32 accumulate helper
__device__ __forceinline__ void acch(float4& a, uint2 v) {
    __half2 p = *(__half2*)&v.x;
    __half2 q = *(__half2*)&v.y;
    float2 fp = __half22float2(p);
    float2 fq = __half22float2(q);
    a.x += fp.x; a.y += fp.y; a.z += fq.x; a.w += fq.y;
}

// ---- gather body: acc += sum_{src in row} hs[src]; indices prefetched+shfl'd
__device__ __forceinline__ void gather_row(float4& acc, const uint2* hs,
                                           int beg, int end, int lane) {
    for (int base = beg; base < end; base += 32) {
        int j = base + lane;
        int myidx = (j < end) ? __ldg(g_csr + j) : 0;
        int cnt = min(32, end - base);
        int jj = 0;
        for (; jj + 8 <= cnt; jj += 8) {
            int s0 = __shfl_sync(0xffffffffu, myidx, jj);
            int s1 = __shfl_sync(0xffffffffu, myidx, jj + 1);
            int s2 = __shfl_sync(0xffffffffu, myidx, jj + 2);
            int s3 = __shfl_sync(0xffffffffu, myidx, jj + 3);
            int s4 = __shfl_sync(0xffffffffu, myidx, jj + 4);
            int s5 = __shfl_sync(0xffffffffu, myidx, jj + 5);
            int s6 = __shfl_sync(0xffffffffu, myidx, jj + 6);
            int s7 = __shfl_sync(0xffffffffu, myidx, jj + 7);
            uint2 v0 = hs[(size_t)s0 * 32 + lane];
            uint2 v1 = hs[(size_t)s1 * 32 + lane];
            uint2 v2 = hs[(size_t)s2 * 32 + lane];
            uint2 v3 = hs[(size_t)s3 * 32 + lane];
            uint2 v4 = hs[(size_t)s4 * 32 + lane];
            uint2 v5 = hs[(size_t)s5 * 32 + lane];
            uint2 v6 = hs[(size_t)s6 * 32 + lane];
            uint2 v7 = hs[(size_t)s7 * 32 + lane];
            acch(acc, v0); acch(acc, v1); acch(acc, v2); acch(acc, v3);
            acch(acc, v4); acch(acc, v5); acch(acc, v6); acch(acc, v7);
        }
        for (; jj + 4 <= cnt; jj += 4) {
            int s0 = __shfl_sync(0xffffffffu, myidx, jj);
            int s1 = __shfl_sync(0xffffffffu, myidx, jj + 1);
            int s2 = __shfl_sync(0xffffffffu, myidx, jj + 2);
            int s3 = __shfl_sync(0xffffffffu, myidx, jj + 3);
            uint2 v0 = hs[(size_t)s0 * 32 + lane];
            uint2 v1 = hs[(size_t)s1 * 32 + lane];
            uint2 v2 = hs[(size_t)s2 * 32 + lane];
            uint2 v3 = hs[(size_t)s3 * 32 + lane];
            acch(acc, v0); acch(acc, v1); acch(acc, v2); acch(acc, v3);
        }
        for (; jj < cnt; jj++) {
            int s = __shfl_sync(0xffffffffu, myidx, jj);
            acch(acc, hs[(size_t)s * 32 + lane]);
        }
    }
}

// -------- gather layer 1: h1 = relu(dinv*(hs1[self] + sum hs1[src]) + b1)
__global__ void k_gather1(const float* __restrict__ b1) {
    int gw = (blockIdx.x * blockDim.x + threadIdx.x) >> 5;
    if (gw >= NN) return;
    int lane = threadIdx.x & 31;
    const uint2* hs = g_hs;
    int beg = __ldg(&g_rowptr[gw]);
    int end = __ldg(&g_rowptr[gw + 1]);
    float4 acc = make_float4(0.f, 0.f, 0.f, 0.f);
    acch(acc, hs[(size_t)gw * 32 + lane]);
    gather_row(acc, hs, beg, end, lane);
    float di = g_dinv[gw];
    float4 b = __ldg(&((const float4*)b1)[lane]);
    float rx = fmaxf(fmaf(di, acc.x, b.x), 0.f);
    float ry = fmaxf(fmaf(di, acc.y, b.y), 0.f);
    float rz = fmaxf(fmaf(di, acc.z, b.z), 0.f);
    float rw = fmaxf(fmaf(di, acc.w, b.w), 0.f);
    __half2 h01 = __floats2half2_rn(rx, ry);
    __half2 h23 = __floats2half2_rn(rz, rw);
    uint2 o;
    o.x = *(unsigned*)&h01;
    o.y = *(unsigned*)&h23;
    g_h1[(size_t)gw * 32 + lane] = o;
}

// ------------------- hs2 = (h1 @ W2) * dinv : HMMA fp16 GEMM, fp32 accum
// block = 256 thr (8 warps); tile M=128, N=128, K=128. smem pad stride 136.
#define KP 136
__global__ void k_gemm() {
    extern __shared__ __half smem_[];
    __half* h1s = smem_;               // [128][KP]
    __half* w2s = smem_ + 128 * KP;    // [n=128][KP]
    const __half* h1 = (const __half*)g_h1;
    __half* hs2 = (__half*)g_hs;
    int tid = threadIdx.x;
    int lane = tid & 31, w = tid >> 5;
    int m0 = blockIdx.x * 128;

    // w2s from precomputed fp16 [n][k]: 8 halves (uint4) per thread x 8 iters
    for (int it = 0; it < 8; it++) {
        int idx = it * 256 + tid;
        int n = idx >> 4, kq = idx & 15;
        uint4 v = *(const uint4*)(g_w2h + n * HD + kq * 8);
        *(uint4*)(w2s + n * KP + kq * 8) = v;
    }
    for (int it = 0; it < 8; it++) {
        int idx = it * 256 + tid;
        int m = idx >> 4, kq = idx & 15;
        int gm = min(m0 + m, NN - 1);
        uint4 v = *(const uint4*)(h1 + (size_t)gm * HD + kq * 8);
        *(uint4*)(h1s + m * KP + kq * 8) = v;
    }
    __syncthreads();

    float acc[16][4];
#pragma unroll
    for (int nt = 0; nt < 16; nt++)
#pragma unroll
        for (int i = 0; i < 4; i++) acc[nt][i] = 0.f;

    int qr = lane >> 2;
    int qc = (lane & 3) * 2;

#pragma unroll
    for (int kt = 0; kt < 8; kt++) {
        const __half* ab = h1s + (w * 16 + qr) * KP + kt * 16 + qc;
        unsigned a0 = *(const unsigned*)(ab);
        unsigned a1 = *(const unsigned*)(ab + 8 * KP);
        unsigned a2 = *(const unsigned*)(ab + 8);
        unsigned a3 = *(const unsigned*)(ab + 8 * KP + 8);
#pragma unroll
        for (int nt = 0; nt < 16; nt++) {
            const __half* bb = w2s + (nt * 8 + qr) * KP + kt * 16 + qc;
            unsigned b0 = *(const unsigned*)(bb);
            unsigned b1 = *(const unsigned*)(bb + 8);
            asm volatile(
                "mma.sync.aligned.m16n8k16.row.col.f32.f16.f16.f32 "
                "{%0,%1,%2,%3}, {%4,%5,%6,%7}, {%8,%9}, {%0,%1,%2,%3};"
                : "+f"(acc[nt][0]), "+f"(acc[nt][1]),
                  "+f"(acc[nt][2]), "+f"(acc[nt][3])
                : "r"(a0), "r"(a1), "r"(a2), "r"(a3), "r"(b0), "r"(b1));
        }
    }

    int r0 = m0 + w * 16 + qr;
    int r1 = r0 + 8;
    float di0 = (r0 < NN) ? g_dinv[r0] : 0.f;
    float di1 = (r1 < NN) ? g_dinv[r1] : 0.f;
#pragma unroll
    for (int nt = 0; nt < 16; nt++) {
        int c = nt * 8 + qc;
        if (r0 < NN) {
            __half2 h = __floats2half2_rn(acc[nt][0] * di0, acc[nt][1] * di0);
            *(__half2*)(hs2 + (size_t)r0 * HD + c) = h;
        }
        if (r1 < NN) {
            __half2 h = __floats2half2_rn(acc[nt][2] * di1, acc[nt][3] * di1);
            *(__half2*)(hs2 + (size_t)r1 * HD + c) = h;
        }
    }
}

// ------- gather layer 2 + pool: pool[batch] += dinv*(hs2[self]+sum)+b2
__global__ void k_gather2(const int* __restrict__ batch, const float* __restrict__ b2) {
    int gw = (blockIdx.x * blockDim.x + threadIdx.x) >> 5;
    if (gw >= NN) return;
    int lane = threadIdx.x & 31;
    const uint2* hs = g_hs;
    int beg = __ldg(&g_rowptr[gw]);
    int end = __ldg(&g_rowptr[gw + 1]);
    float4 acc = make_float4(0.f, 0.f, 0.f, 0.f);
    acch(acc, hs[(size_t)gw * 32 + lane]);
    gather_row(acc, hs, beg, end, lane);
    float di = g_dinv[gw];
    float4 b = __ldg(&((const float4*)b2)[lane]);
    float4 r;
    r.x = fmaf(di, acc.x, b.x);
    r.y = fmaf(di, acc.y, b.y);
    r.z = fmaf(di, acc.z, b.z);
    r.w = fmaf(di, acc.w, b.w);
    atomicAdd(&g_pool[(size_t)__ldg(&batch[gw]) * 32 + lane], r);
}

// ------------------------------- out[g] = (pool[g]/max(cnt,1)) @ Wlin + blin
__global__ void k_out(const float* __restrict__ Wlin, const float* __restrict__ blin,
                      float* __restrict__ out) {
    __shared__ float p[HD];
    int g = blockIdx.x;
    int t = threadIdx.x;
    float c = (float)g_cnt_i[g];
    c = (c < 1.f) ? 1.f : c;
    p[t] = ((const float*)g_pool)[(size_t)g * HD + t] / c;
    __syncthreads();
    if (t < FOUT) {
        float s = blin[t];
#pragma unroll 8
        for (int k = 0; k < HD; k++) s = fmaf(p[k], Wlin[k * FOUT + t], s);
        out[(size_t)g * FOUT + t] = s;
    }
}

extern "C" void kernel_launch(void* const* d_in, const int* in_sizes, int n_in,
                              void* d_out, int out_size) {
    (void)in_sizes; (void)n_in; (void)out_size;
    const float* x     = (const float*)d_in[0];
    const int*   esrc  = (const int*)d_in[1];
    const int*   edst  = (const int*)d_in[2];
    const int*   batch = (const int*)d_in[3];
    const float* W1    = (const float*)d_in[4];
    const float* b1    = (const float*)d_in[5];
    const float* W2    = (const float*)d_in[6];
    const float* b2    = (const float*)d_in[7];
    const float* Wlin  = (const float*)d_in[8];
    const float* blin  = (const float*)d_in[9];
    float* out = (float*)d_out;

    const int DSMEM = 2 * 128 * KP * (int)sizeof(__half);   // 69632 B
    cudaFuncSetAttribute(k_gemm, cudaFuncAttributeMaxDynamicSharedMemorySize, DSMEM);

    k_zero<<<512, 256>>>(W2);
    k_degcnt<<<2048, 256>>>(edst, batch);
    k_scanA<<<NBLK, 512>>>();
    k_scanC<<<NBLK, 512>>>();
    k_fill<<<2048, 256>>>(esrc, edst);
    k_xw1<<<12500, 256>>>(x, W1);
    k_gather1<<<12500, 256>>>(b1);
    k_gemm<<<(NN + 127) / 128, 256, DSMEM>>>();
    k_gather2<<<12500, 256>>>(batch, b2);
    k_out<<<NG, HD>>>(Wlin, blin, out);
}